// round 11
// baseline (speedup 1.0000x reference)
#include <cuda_runtime.h>

// MultiHeadAttentionQuantum — closed-form reduction (R1 derivation):
//   c_u = cos(q_u + phi_u);  out_w = prod_{u<=w} c_u (w>=1);  out_0 = prod_{u=1..7} c_u
//   y = Wc @ out + bc.  k/v are dead code in the reference.
//
// R11: R10 shape (2 tok/thread, halves-split coalesced LDG.128, block=128,
// grid=128) but NO smem / NO barrier: weights read via warp-uniform LDG
// broadcast (9 lines, L2-resident across graph replays). Every warp runs a
// fully independent chain; all loads front-batched.

#define E_DIM 8
#define N_TOK 32768
#define HALF  (N_TOK / 2)      // 16384

__global__ __launch_bounds__(128)
void mhaq_kernel(const float* __restrict__ x,
                 const float* __restrict__ Wq, const float* __restrict__ bq,
                 const float* __restrict__ Wc, const float* __restrict__ bc,
                 const float* __restrict__ phi,
                 float* __restrict__ out)
{
    int gtid = blockIdx.x * 128 + threadIdx.x;    // 0 .. HALF-1
    int tA = gtid;
    int tB = gtid + HALF;

    // Front-batch the four x loads (coalesced, 8 lines/req) ...
    const float4* xv = reinterpret_cast<const float4*>(x);
    float4 a0 = xv[2 * tA];
    float4 a1 = xv[2 * tA + 1];
    float4 b0 = xv[2 * tB];
    float4 b1 = xv[2 * tB + 1];

    // ... and the warp-uniform weight loads (broadcast: 1 request/warp/line).
    const float4* Wq4 = reinterpret_cast<const float4*>(Wq);
    const float4* Wc4 = reinterpret_cast<const float4*>(Wc);
    float4 wq[16], wc[16];
    #pragma unroll
    for (int i = 0; i < 16; i++) wq[i] = __ldg(&Wq4[i]);
    #pragma unroll
    for (int i = 0; i < 16; i++) wc[i] = __ldg(&Wc4[i]);

    const float4* bq4  = reinterpret_cast<const float4*>(bq);
    const float4* bc4  = reinterpret_cast<const float4*>(bc);
    const float4* phi4 = reinterpret_cast<const float4*>(phi);
    float4 bqa = __ldg(&bq4[0]),  bqb = __ldg(&bq4[1]);
    float4 pha = __ldg(&phi4[0]), phb = __ldg(&phi4[1]);
    float4 bca = __ldg(&bc4[0]),  bcb = __ldg(&bc4[1]);

    float bqp[8] = {bqa.x + pha.x, bqa.y + pha.y, bqa.z + pha.z, bqa.w + pha.w,
                    bqb.x + phb.x, bqb.y + phb.y, bqb.z + phb.z, bqb.w + phb.w};
    float bcr[8] = {bca.x, bca.y, bca.z, bca.w, bcb.x, bcb.y, bcb.z, bcb.w};

    float xa[8] = {a0.x, a0.y, a0.z, a0.w, a1.x, a1.y, a1.z, a1.w};
    float xb[8] = {b0.x, b0.y, b0.z, b0.w, b1.x, b1.y, b1.z, b1.w};

    // q = Wq @ x + (bq+phi); c = cos(q). Two independent streams for ILP.
    float cA[8], cB[8];
    #pragma unroll
    for (int u = 0; u < 8; u++) {
        float4 w0 = wq[u * 2], w1 = wq[u * 2 + 1];
        float qa = bqp[u], qb = bqp[u];
        qa = fmaf(w0.x, xa[0], qa); qb = fmaf(w0.x, xb[0], qb);
        qa = fmaf(w0.y, xa[1], qa); qb = fmaf(w0.y, xb[1], qb);
        qa = fmaf(w0.z, xa[2], qa); qb = fmaf(w0.z, xb[2], qb);
        qa = fmaf(w0.w, xa[3], qa); qb = fmaf(w0.w, xb[3], qb);
        qa = fmaf(w1.x, xa[4], qa); qb = fmaf(w1.x, xb[4], qb);
        qa = fmaf(w1.y, xa[5], qa); qb = fmaf(w1.y, xb[5], qb);
        qa = fmaf(w1.z, xa[6], qa); qb = fmaf(w1.z, xb[6], qb);
        qa = fmaf(w1.w, xa[7], qa); qb = fmaf(w1.w, xb[7], qb);
        cA[u] = __cosf(qa);
        cB[u] = __cosf(qb);
    }

    // Prefix products for both tokens.
    float oA[8], oB[8];
    {
        float pa = cA[0], pb = cB[0];
        #pragma unroll
        for (int w = 1; w < 8; w++) {
            pa *= cA[w]; oA[w] = pa;
            pb *= cB[w]; oB[w] = pb;
        }
        float sa = cA[1], sb = cB[1];
        #pragma unroll
        for (int w = 2; w < 8; w++) { sa *= cA[w]; sb *= cB[w]; }
        oA[0] = sa; oB[0] = sb;
    }

    // y = Wc @ o + bc for both tokens.
    float yA[8], yB[8];
    #pragma unroll
    for (int u = 0; u < 8; u++) {
        float4 w0 = wc[u * 2], w1 = wc[u * 2 + 1];
        float va = bcr[u], vb = bcr[u];
        va = fmaf(w0.x, oA[0], va); vb = fmaf(w0.x, oB[0], vb);
        va = fmaf(w0.y, oA[1], va); vb = fmaf(w0.y, oB[1], vb);
        va = fmaf(w0.z, oA[2], va); vb = fmaf(w0.z, oB[2], vb);
        va = fmaf(w0.w, oA[3], va); vb = fmaf(w0.w, oB[3], vb);
        va = fmaf(w1.x, oA[4], va); vb = fmaf(w1.x, oB[4], vb);
        va = fmaf(w1.y, oA[5], va); vb = fmaf(w1.y, oB[5], vb);
        va = fmaf(w1.z, oA[6], va); vb = fmaf(w1.z, oB[6], vb);
        va = fmaf(w1.w, oA[7], va); vb = fmaf(w1.w, oB[7], vb);
        yA[u] = va; yB[u] = vb;
    }

    float4* ov = reinterpret_cast<float4*>(out);
    ov[2 * tA]     = make_float4(yA[0], yA[1], yA[2], yA[3]);
    ov[2 * tA + 1] = make_float4(yA[4], yA[5], yA[6], yA[7]);
    ov[2 * tB]     = make_float4(yB[0], yB[1], yB[2], yB[3]);
    ov[2 * tB + 1] = make_float4(yB[4], yB[5], yB[6], yB[7]);
}

extern "C" void kernel_launch(void* const* d_in, const int* in_sizes, int n_in,
                              void* d_out, int out_size)
{
    // metadata order: x, Wq, bq, Wk, bk, Wv, bv, Wc, bc, phi
    const float* x   = (const float*)d_in[0];
    const float* Wq  = (const float*)d_in[1];
    const float* bq  = (const float*)d_in[2];
    const float* Wc  = (const float*)d_in[7];
    const float* bc  = (const float*)d_in[8];
    const float* phi = (const float*)d_in[9];
    float* out = (float*)d_out;

    mhaq_kernel<<<HALF / 128, 128>>>(x, Wq, bq, Wc, bc, phi, out);
}

// round 13
// speedup vs baseline: 1.0804x; 1.0804x over previous
#include <cuda_runtime.h>

// MultiHeadAttentionQuantum — closed-form reduction (R1 derivation):
//   c_u = cos(q_u + phi_u);  out_w = prod_{u<=w} c_u (w>=1);  out_0 = prod_{u=1..7} c_u
//   y = Wc @ out + bc.  k/v are dead code in the reference.
//
// R13 = R12 resubmit (R12 bench was an infra failure, never measured).
// Locked family (R8/R10: bench 6.40/6.66, best ncu durs): 2 tokens/thread,
// halves-split coalesced LDG.128, block=128, grid=128, smem-staged weights,
// MLP=4 front-batch, 2-way ILP. Micro-tweaks: streaming (.cs) stores; token-A
// epilogue stored before token-B's output matvec (shorter warp tail).

#define E_DIM 8
#define N_TOK 32768
#define HALF  (N_TOK / 2)      // 16384

__device__ __forceinline__ void stg_cs_f4(float4* p, float4 v) {
    asm volatile("st.global.cs.v4.f32 [%0], {%1, %2, %3, %4};"
                 :: "l"(p), "f"(v.x), "f"(v.y), "f"(v.z), "f"(v.w) : "memory");
}

__global__ __launch_bounds__(128)
void mhaq_kernel(const float* __restrict__ x,
                 const float* __restrict__ Wq, const float* __restrict__ bq,
                 const float* __restrict__ Wc, const float* __restrict__ bc,
                 const float* __restrict__ phi,
                 float* __restrict__ out)
{
    __shared__ float4 sWq[16], sWc[16];
    __shared__ float  sBqp[8], sBc[8];

    int tid = threadIdx.x;
    int gtid = blockIdx.x * 128 + tid;            // 0 .. HALF-1
    int tA = gtid;
    int tB = gtid + HALF;

    // Front-batch all four x loads (independent, MLP=4, coalesced 8 lines/req).
    const float4* xv = reinterpret_cast<const float4*>(x);
    float4 a0 = xv[2 * tA];
    float4 a1 = xv[2 * tA + 1];
    float4 b0 = xv[2 * tB];
    float4 b1 = xv[2 * tB + 1];

    // Stage weights in shared while the x loads are in flight.
    if (tid < 16) {
        sWq[tid] = reinterpret_cast<const float4*>(Wq)[tid];
        sWc[tid] = reinterpret_cast<const float4*>(Wc)[tid];
    }
    if (tid < 8) {
        sBqp[tid] = bq[tid] + phi[tid];
        sBc[tid]  = bc[tid];
    }
    __syncthreads();

    float xa[8] = {a0.x, a0.y, a0.z, a0.w, a1.x, a1.y, a1.z, a1.w};
    float xb[8] = {b0.x, b0.y, b0.z, b0.w, b1.x, b1.y, b1.z, b1.w};

    // q = Wq @ x + (bq+phi); c = cos(q). Two independent streams for ILP.
    float cA[8], cB[8];
    #pragma unroll
    for (int u = 0; u < 8; u++) {
        float4 w0 = sWq[u * 2], w1 = sWq[u * 2 + 1];
        float base = sBqp[u];
        float qa = base, qb = base;
        qa = fmaf(w0.x, xa[0], qa); qb = fmaf(w0.x, xb[0], qb);
        qa = fmaf(w0.y, xa[1], qa); qb = fmaf(w0.y, xb[1], qb);
        qa = fmaf(w0.z, xa[2], qa); qb = fmaf(w0.z, xb[2], qb);
        qa = fmaf(w0.w, xa[3], qa); qb = fmaf(w0.w, xb[3], qb);
        qa = fmaf(w1.x, xa[4], qa); qb = fmaf(w1.x, xb[4], qb);
        qa = fmaf(w1.y, xa[5], qa); qb = fmaf(w1.y, xb[5], qb);
        qa = fmaf(w1.z, xa[6], qa); qb = fmaf(w1.z, xb[6], qb);
        qa = fmaf(w1.w, xa[7], qa); qb = fmaf(w1.w, xb[7], qb);
        cA[u] = __cosf(qa);
        cB[u] = __cosf(qb);
    }

    // Prefix products for both tokens.
    float oA[8], oB[8];
    {
        float pa = cA[0], pb = cB[0];
        #pragma unroll
        for (int w = 1; w < 8; w++) {
            pa *= cA[w]; oA[w] = pa;
            pb *= cB[w]; oB[w] = pb;
        }
        float sa = cA[1], sb = cB[1];
        #pragma unroll
        for (int w = 2; w < 8; w++) { sa *= cA[w]; sb *= cB[w]; }
        oA[0] = sa; oB[0] = sb;
    }

    float4* ov = reinterpret_cast<float4*>(out);

    // Token A output matvec, stored immediately (shortens warp tail).
    {
        float yA[8];
        #pragma unroll
        for (int u = 0; u < 8; u++) {
            float4 w0 = sWc[u * 2], w1 = sWc[u * 2 + 1];
            float va = sBc[u];
            va = fmaf(w0.x, oA[0], va); va = fmaf(w0.y, oA[1], va);
            va = fmaf(w0.z, oA[2], va); va = fmaf(w0.w, oA[3], va);
            va = fmaf(w1.x, oA[4], va); va = fmaf(w1.y, oA[5], va);
            va = fmaf(w1.z, oA[6], va); va = fmaf(w1.w, oA[7], va);
            yA[u] = va;
        }
        stg_cs_f4(&ov[2 * tA],     make_float4(yA[0], yA[1], yA[2], yA[3]));
        stg_cs_f4(&ov[2 * tA + 1], make_float4(yA[4], yA[5], yA[6], yA[7]));
    }

    // Token B output matvec + store.
    {
        float yB[8];
        #pragma unroll
        for (int u = 0; u < 8; u++) {
            float4 w0 = sWc[u * 2], w1 = sWc[u * 2 + 1];
            float vb = sBc[u];
            vb = fmaf(w0.x, oB[0], vb); vb = fmaf(w0.y, oB[1], vb);
            vb = fmaf(w0.z, oB[2], vb); vb = fmaf(w0.w, oB[3], vb);
            vb = fmaf(w1.x, oB[4], vb); vb = fmaf(w1.y, oB[5], vb);
            vb = fmaf(w1.z, oB[6], vb); vb = fmaf(w1.w, oB[7], vb);
            yB[u] = vb;
        }
        stg_cs_f4(&ov[2 * tB],     make_float4(yB[0], yB[1], yB[2], yB[3]));
        stg_cs_f4(&ov[2 * tB + 1], make_float4(yB[4], yB[5], yB[6], yB[7]));
    }
}

extern "C" void kernel_launch(void* const* d_in, const int* in_sizes, int n_in,
                              void* d_out, int out_size)
{
    // metadata order: x, Wq, bq, Wk, bk, Wv, bv, Wc, bc, phi
    const float* x   = (const float*)d_in[0];
    const float* Wq  = (const float*)d_in[1];
    const float* bq  = (const float*)d_in[2];
    const float* Wc  = (const float*)d_in[7];
    const float* bc  = (const float*)d_in[8];
    const float* phi = (const float*)d_in[9];
    float* out = (float*)d_out;

    mhaq_kernel<<<HALF / 128, 128>>>(x, Wq, bq, Wc, bc, phi, out);
}